// round 8
// baseline (speedup 1.0000x reference)
#include <cuda_runtime.h>
#include <cuda_fp16.h>
#include <cuda_bf16.h>
#include <math.h>
#include <stdint.h>

#define LNF 128      // feat dim
#define SS  32       // stat dim
#define CC  10       // classes
#define NPQ 2048     // P(1024) || Q(1024)
#define MAXV 50000
#define MAXE 200000
#define MU_OVER_S (0.9f / 32.0f)
#define SCAN_BLK 512
#define MAXB ((MAXV + SCAN_BLK - 1) / SCAN_BLK)   // 98

// -------- static device scratch --------
__device__ __half         g_PQh[(size_t)MAXV * NPQ];  // fp16 P|Q (bxi folded into P)
__device__ __nv_bfloat16  g_W2b[LNF * NPQ];           // bf16 [128 x 2048]
__device__ __nv_bfloat16  g_fb[(size_t)MAXV * LNF];   // bf16 feat
__device__ float          g_R[MAXV * SS];             // fp32 R
__device__ float          g_hacc[MAXV * SS];
__device__ int            g_cnt[MAXV];
__device__ int            g_fill[MAXV];
__device__ int            g_off[MAXV + 1];
__device__ int            g_bsum[MAXB];
__device__ int            g_ev[MAXE];
__device__ float          g_esc[MAXE];

__device__ __forceinline__ __half2 h2tanh_fast(__half2 x) {
    uint32_t xi = *(uint32_t*)&x, yi;
    asm("tanh.approx.f16x2 %0, %1;" : "=r"(yi) : "r"(xi));
    return *(__half2*)&yi;
}

// ---------------- packing + cnt zero (fused) ----------------
__global__ void pack_w2_kernel(const float* __restrict__ Wxi, int V) {
    int idx = blockIdx.x * blockDim.x + threadIdx.x;
    if (idx < V) g_cnt[idx] = 0;
    if (idx >= LNF * NPQ) return;
    int k = idx / NPQ, j = idx - k * NPQ;
    float v = (j < 1024) ? Wxi[k * 1024 + j] : Wxi[(k + LNF) * 1024 + (j - 1024)];
    g_W2b[idx] = __float2bfloat16(v);
}

// ---------------- CSR build ----------------
__global__ void count_kernel(const int* __restrict__ Xn, int E) {
    int e = blockIdx.x * blockDim.x + threadIdx.x;
    if (e < E) atomicAdd(&g_cnt[Xn[e]], 1);
}

__global__ __launch_bounds__(SCAN_BLK) void scan1_kernel(int V) {
    __shared__ int s[SCAN_BLK];
    int i = blockIdx.x * SCAN_BLK + threadIdx.x;
    s[threadIdx.x] = (i < V) ? g_cnt[i] : 0;
    __syncthreads();
#pragma unroll
    for (int off = SCAN_BLK / 2; off > 0; off >>= 1) {
        if (threadIdx.x < off) s[threadIdx.x] += s[threadIdx.x + off];
        __syncthreads();
    }
    if (threadIdx.x == 0) g_bsum[blockIdx.x] = s[0];
}

__global__ __launch_bounds__(128) void scan2_kernel(int nb, int V) {
    __shared__ int s[128];
    int t = threadIdx.x;
    int v = (t < nb) ? g_bsum[t] : 0;
    s[t] = v;
    __syncthreads();
#pragma unroll
    for (int off = 1; off < 128; off <<= 1) {
        int x = (t >= off) ? s[t - off] : 0;
        __syncthreads();
        s[t] += x;
        __syncthreads();
    }
    if (t < nb) g_bsum[t] = s[t] - v;        // exclusive
    if (t == 127) g_off[V] = s[127];          // total
}

__global__ __launch_bounds__(SCAN_BLK) void scan3_kernel(int V) {
    __shared__ int s[SCAN_BLK];
    int i = blockIdx.x * SCAN_BLK + threadIdx.x;
    int v = (i < V) ? g_cnt[i] : 0;
    s[threadIdx.x] = v;
    __syncthreads();
#pragma unroll
    for (int off = 1; off < SCAN_BLK; off <<= 1) {
        int x = (threadIdx.x >= off) ? s[threadIdx.x - off] : 0;
        __syncthreads();
        s[threadIdx.x] += x;
        __syncthreads();
    }
    if (i < V) {
        g_off[i]  = g_bsum[blockIdx.x] + s[threadIdx.x] - v;   // exclusive
        g_fill[i] = 0;
    }
}

__global__ void fill_kernel(const int* __restrict__ Xn, const int* __restrict__ Xe,
                            const float* __restrict__ dg, int E) {
    int e = blockIdx.x * blockDim.x + threadIdx.x;
    if (e >= E) return;
    int u = Xn[e];
    int pos = g_off[u] + atomicAdd(&g_fill[u], 1);
    g_ev[pos]  = Xe[e];
    g_esc[pos] = MU_OVER_S / dg[e];
}

// ---------------- bf16 MMA GEMM: PQ[M x 2048] = featbf[M x 128] @ W2b ----------------
#define AS_STRIDE 136
#define SMEM_B_OFF (128 * AS_STRIDE)
#define GEMM_SMEM_BYTES (2 * 128 * AS_STRIDE * 2)

__device__ __forceinline__ void ldsm_x4(uint32_t& r0, uint32_t& r1, uint32_t& r2, uint32_t& r3,
                                        uint32_t addr) {
    asm volatile("ldmatrix.sync.aligned.m8n8.x4.shared.b16 {%0,%1,%2,%3}, [%4];"
                 : "=r"(r0), "=r"(r1), "=r"(r2), "=r"(r3) : "r"(addr));
}
__device__ __forceinline__ void ldsm_x4_t(uint32_t& r0, uint32_t& r1, uint32_t& r2, uint32_t& r3,
                                          uint32_t addr) {
    asm volatile("ldmatrix.sync.aligned.m8n8.x4.trans.shared.b16 {%0,%1,%2,%3}, [%4];"
                 : "=r"(r0), "=r"(r1), "=r"(r2), "=r"(r3) : "r"(addr));
}
__device__ __forceinline__ void mma_bf16(float* c, const uint32_t* a, uint32_t b0, uint32_t b1) {
    asm volatile(
        "mma.sync.aligned.m16n8k16.row.col.f32.bf16.bf16.f32 "
        "{%0,%1,%2,%3}, {%4,%5,%6,%7}, {%8,%9}, {%0,%1,%2,%3};\n"
        : "+f"(c[0]), "+f"(c[1]), "+f"(c[2]), "+f"(c[3])
        : "r"(a[0]), "r"(a[1]), "r"(a[2]), "r"(a[3]), "r"(b0), "r"(b1));
}
__device__ __forceinline__ void cp_async16(uint32_t saddr, const void* gaddr) {
    asm volatile("cp.async.cg.shared.global [%0], [%1], 16;" :: "r"(saddr), "l"(gaddr));
}

__global__ __launch_bounds__(256) void gemm_bf16_kernel(const float* __restrict__ bxi, int M) {
    extern __shared__ __nv_bfloat16 smem[];

    const int tid  = threadIdx.x;
    const int warp = tid >> 5;
    const int lane = tid & 31;
    const int g    = lane >> 2;
    const int t4   = lane & 3;
    const int wm   = warp & 3;
    const int wn   = warp >> 2;
    const int row0 = blockIdx.y * 128;
    const int col0 = blockIdx.x * 128;

    uint32_t smem_base;
    asm("{ .reg .u64 t; cvta.to.shared.u64 t, %1; cvt.u32.u64 %0, t; }"
        : "=r"(smem_base) : "l"(smem));

#pragma unroll
    for (int i = 0; i < 8; ++i) {
        int c = tid + i * 256;
        int r = c >> 4;
        int seg = c & 15;
        int grow = row0 + r; if (grow >= M) grow = M - 1;
        cp_async16(smem_base + (uint32_t)(r * AS_STRIDE + seg * 8) * 2,
                   g_fb + (size_t)grow * LNF + seg * 8);
        cp_async16(smem_base + (uint32_t)(SMEM_B_OFF + r * AS_STRIDE + seg * 8) * 2,
                   g_W2b + (size_t)r * NPQ + col0 + seg * 8);
    }
    asm volatile("cp.async.commit_group;");
    asm volatile("cp.async.wait_group 0;");
    __syncthreads();

    float acc[2][8][4];
#pragma unroll
    for (int mt = 0; mt < 2; ++mt)
#pragma unroll
        for (int nt = 0; nt < 8; ++nt)
#pragma unroll
            for (int r = 0; r < 4; ++r) acc[mt][nt][r] = 0.0f;

#pragma unroll
    for (int ks = 0; ks < 8; ++ks) {
        const int kb = ks * 16;
        uint32_t a[2][4];
#pragma unroll
        for (int mt = 0; mt < 2; ++mt) {
            int ar = wm * 32 + mt * 16;
            uint32_t addr = smem_base +
                (uint32_t)((ar + (lane & 15)) * AS_STRIDE + kb + ((lane >> 4) << 3)) * 2;
            ldsm_x4(a[mt][0], a[mt][1], a[mt][2], a[mt][3], addr);
        }
#pragma unroll
        for (int np = 0; np < 4; ++np) {
            int nc = wn * 64 + np * 16;
            uint32_t b0, b1, b2, b3;
            uint32_t addr = smem_base +
                (uint32_t)(SMEM_B_OFF + (kb + (lane & 15)) * AS_STRIDE + nc + ((lane >> 4) << 3)) * 2;
            ldsm_x4_t(b0, b1, b2, b3, addr);
#pragma unroll
            for (int mt = 0; mt < 2; ++mt) {
                mma_bf16(acc[mt][np * 2],     a[mt], b0, b1);
                mma_bf16(acc[mt][np * 2 + 1], a[mt], b2, b3);
            }
        }
    }

#pragma unroll
    for (int mt = 0; mt < 2; ++mt) {
        int rlo = row0 + wm * 32 + mt * 16 + g;
#pragma unroll
        for (int nt = 0; nt < 8; ++nt) {
            int c = col0 + wn * 64 + nt * 8 + 2 * t4;
            float b0 = 0.f, b1 = 0.f;
            if (c < 1024) { b0 = __ldg(&bxi[c]); b1 = __ldg(&bxi[c + 1]); }
            if (rlo < M)
                __stcs((__half2*)(g_PQh + (size_t)rlo * NPQ + c),
                       __floats2half2_rn(acc[mt][nt][0] + b0, acc[mt][nt][1] + b1));
            if (rlo + 8 < M)
                __stcs((__half2*)(g_PQh + (size_t)(rlo + 8) * NPQ + c),
                       __floats2half2_rn(acc[mt][nt][2] + b0, acc[mt][nt][3] + b1));
        }
    }
}

// ---------------- R kernel (fp32) + fused feat->bf16 conversion ----------------
#define RNODES 48
__global__ __launch_bounds__(256) void r_kernel(const float* __restrict__ feat,
                                                const float* __restrict__ Wrou,
                                                const float* __restrict__ brou, int V) {
    __shared__ float Ws[LNF * SS];
    __shared__ float fr[RNODES * LNF];
    const int tid = threadIdx.x;
    const int n0 = blockIdx.x * RNODES;

    for (int i = tid; i < LNF * SS; i += 256) Ws[i] = Wrou[i];
    for (int i = tid; i < RNODES * LNF / 4; i += 256) {
        int node = n0 + (i * 4) / LNF;
        if (node >= V) node = V - 1;
        int k = (i * 4) & (LNF - 1);
        *(float4*)&fr[i * 4] = *(const float4*)(feat + (size_t)node * LNF + k);
    }
    __syncthreads();

    for (int i = tid; i < RNODES * LNF / 2; i += 256) {
        int node = n0 + (i * 2) / LNF;
        if (node < V) {
            int k = (i * 2) & (LNF - 1);
            ((__nv_bfloat162*)(g_fb + (size_t)node * LNF + k))[0] =
                __floats2bfloat162_rn(fr[i * 2], fr[i * 2 + 1]);
        }
    }

    const int warp = tid >> 5, lane = tid & 31;
    float acc[6];
#pragma unroll
    for (int i = 0; i < 6; ++i) acc[i] = 0.0f;
    const float* fbase = &fr[warp * 6 * LNF];
#pragma unroll 16
    for (int k = 0; k < LNF; ++k) {
        float wv = Ws[k * SS + lane];
#pragma unroll
        for (int i = 0; i < 6; ++i) acc[i] = fmaf(fbase[i * LNF + k], wv, acc[i]);
    }
    float bb = brou[lane];
#pragma unroll
    for (int i = 0; i < 6; ++i) {
        int node = n0 + warp * 6 + i;
        if (node < V) g_R[node * SS + lane] = tanhf(acc[i] + bb);
    }
}

// ---------------- edge kernel: warp/node, half the S-rows per pass, MLP-4 chunks ----------------
__global__ __launch_bounds__(256) void edge_half_kernel(int V, int pass) {
    __shared__ float rs[8][SS];
    const int warp = threadIdx.x >> 5;
    const int lane = threadIdx.x & 31;
    const int u = blockIdx.x * 8 + warp;
    if (u >= V) return;
    const int n = g_cnt[u];
    if (n == 0) return;
    const int start = g_off[u];
    const int end = start + n;

    rs[warp][lane] = g_R[u * SS + lane];
    __syncwarp();

    const int row = lane >> 1;            // 0..15 local output row
    const int jh  = (lane & 1) * 16;      // j offset 0 or 16
    const size_t eoff = (size_t)pass * 512 + row * 32 + jh;

    float rloc[16];
#pragma unroll
    for (int i = 0; i < 16; ++i) rloc[i] = rs[warp][jh + i];

    const uint4 pA = __ldcs((const uint4*)(g_PQh + (size_t)u * NPQ + eoff));
    const uint4 pB = __ldcs((const uint4*)(g_PQh + (size_t)u * NPQ + eoff + 8));

    float racc = 0.0f;
    for (int e = start; e < end; e += 4) {
        const int m = end - e;            // >=1
        uint4 qa[4], qb[4];
        float scv[4];
        // issue all gathers first: MLP=4
#pragma unroll
        for (int i = 0; i < 4; ++i) {
            if (i < m) {
                const int v = g_ev[e + i];
                scv[i] = g_esc[e + i];
                const uint4* qp = (const uint4*)(g_PQh + (size_t)v * NPQ + 1024 + eoff);
                qa[i] = qp[0];
                qb[i] = qp[1];
            }
        }
#pragma unroll
        for (int i = 0; i < 4; ++i) {
            if (i < m) {
                float partial = 0.0f;
                const __half2* ph = (const __half2*)&pA;
                const __half2* qh = (const __half2*)&qa[i];
#pragma unroll
                for (int k = 0; k < 4; ++k) {
                    float2 t = __half22float2(h2tanh_fast(__hadd2(ph[k], qh[k])));
                    partial = fmaf(t.x, rloc[2 * k],     partial);
                    partial = fmaf(t.y, rloc[2 * k + 1], partial);
                }
                ph = (const __half2*)&pB; qh = (const __half2*)&qb[i];
#pragma unroll
                for (int k = 0; k < 4; ++k) {
                    float2 t = __half22float2(h2tanh_fast(__hadd2(ph[k], qh[k])));
                    partial = fmaf(t.x, rloc[8 + 2 * k],     partial);
                    partial = fmaf(t.y, rloc[8 + 2 * k + 1], partial);
                }
                racc = fmaf(partial, scv[i], racc);
            }
        }
    }

    racc += __shfl_down_sync(0xffffffffu, racc, 1, 2);
    if ((lane & 1) == 0)
        g_hacc[u * SS + pass * 16 + row] = racc;
}

// ---------------- output ----------------
__global__ __launch_bounds__(256) void out_kernel(const float* __restrict__ Wout,
                                                  const float* __restrict__ bout,
                                                  float* __restrict__ out, int V) {
    int gtid = blockIdx.x * blockDim.x + threadIdx.x;
    int vtx = gtid >> 5;
    int lane = threadIdx.x & 31;
    if (vtx >= V) return;

    float c = (float)g_cnt[vtx];
    float Hf = (c > 0.0f) ? c * (g_hacc[vtx * SS + lane] + g_R[vtx * SS + lane]) : 0.0f;

    float mine = 0.0f;
    float logits[CC];
#pragma unroll
    for (int j = 0; j < CC; ++j) {
        float p = Hf * Wout[lane * CC + j];
#pragma unroll
        for (int off = 16; off > 0; off >>= 1)
            p += __shfl_xor_sync(0xffffffffu, p, off);
        logits[j] = p + bout[j];
        if (j == lane) mine = logits[j];
    }
    float m = logits[0];
#pragma unroll
    for (int j = 1; j < CC; ++j) m = fmaxf(m, logits[j]);
    float se = 0.0f;
#pragma unroll
    for (int j = 0; j < CC; ++j) se += expf(logits[j] - m);
    float lse = m + logf(se);

    if (lane < CC) out[(size_t)vtx * CC + lane] = mine - lse;
}

// ---------------- launch ----------------
extern "C" void kernel_launch(void* const* d_in, const int* in_sizes, int n_in,
                              void* d_out, int out_size) {
    const float* feat = (const float*)d_in[0];
    const int*   Xn   = (const int*)d_in[1];
    const int*   Xe   = (const int*)d_in[2];
    const float* dg   = (const float*)d_in[3];
    const float* Wxi  = (const float*)d_in[4];
    const float* bxi  = (const float*)d_in[5];
    const float* Wrou = (const float*)d_in[6];
    const float* brou = (const float*)d_in[7];
    const float* Wout = (const float*)d_in[8];
    const float* bout = (const float*)d_in[9];
    float* out = (float*)d_out;

    const int V = in_sizes[0] / LNF;
    const int E = in_sizes[1];
    const int nb = (V + SCAN_BLK - 1) / SCAN_BLK;

    cudaFuncSetAttribute(gemm_bf16_kernel,
                         cudaFuncAttributeMaxDynamicSharedMemorySize, GEMM_SMEM_BYTES);

    pack_w2_kernel<<<(LNF * NPQ + 255) / 256, 256>>>(Wxi, V);   // also zeroes g_cnt
    count_kernel<<<(E + 255) / 256, 256>>>(Xn, E);
    scan1_kernel<<<nb, SCAN_BLK>>>(V);
    scan2_kernel<<<1, 128>>>(nb, V);
    scan3_kernel<<<nb, SCAN_BLK>>>(V);
    fill_kernel<<<(E + 255) / 256, 256>>>(Xn, Xe, dg, E);

    r_kernel<<<(V + RNODES - 1) / RNODES, 256>>>(feat, Wrou, brou, V);   // also writes g_fb

    dim3 ggrid(NPQ / 128, (V + 127) / 128);
    gemm_bf16_kernel<<<ggrid, 256, GEMM_SMEM_BYTES>>>(bxi, V);

    edge_half_kernel<<<(V + 7) / 8, 256>>>(V, 0);
    edge_half_kernel<<<(V + 7) / 8, 256>>>(V, 1);
    out_kernel<<<(V * 32 + 255) / 256, 256>>>(Wout, bout, out, V);
}

// round 9
// speedup vs baseline: 1.0485x; 1.0485x over previous
#include <cuda_runtime.h>
#include <cuda_fp16.h>
#include <cuda_bf16.h>
#include <math.h>
#include <stdint.h>

#define LNF 128      // feat dim
#define SS  32       // stat dim
#define CC  10       // classes
#define NPQ 2048     // P(1024) || Q(1024)
#define MAXV 50000
#define MAXE 200000
#define MU_OVER_S (0.9f / 32.0f)
#define SCAN_BLK 512
#define MAXB ((MAXV + SCAN_BLK - 1) / SCAN_BLK)   // 98

// -------- static device scratch --------
__device__ __half         g_PQh[(size_t)MAXV * NPQ];  // fp16 P|Q (bxi folded into P)
__device__ __nv_bfloat16  g_W2b[LNF * NPQ];           // bf16 [128 x 2048]
__device__ __nv_bfloat16  g_fb[(size_t)MAXV * LNF];   // bf16 feat
__device__ float          g_R[MAXV * SS];             // fp32 R
__device__ float          g_hacc[MAXV * SS];
__device__ int            g_cnt[MAXV];
__device__ int            g_fill[MAXV];
__device__ int            g_off[MAXV + 1];
__device__ int            g_bsum[MAXB];
__device__ int            g_ev[MAXE];
__device__ float          g_esc[MAXE];

__device__ __forceinline__ __half2 h2tanh_fast(__half2 x) {
    uint32_t xi = *(uint32_t*)&x, yi;
    asm("tanh.approx.f16x2 %0, %1;" : "=r"(yi) : "r"(xi));
    return *(__half2*)&yi;
}

// ---------------- packing + cnt zero (fused) ----------------
__global__ void pack_w2_kernel(const float* __restrict__ Wxi, int V) {
    int idx = blockIdx.x * blockDim.x + threadIdx.x;
    if (idx < V) g_cnt[idx] = 0;
    if (idx >= LNF * NPQ) return;
    int k = idx / NPQ, j = idx - k * NPQ;
    float v = (j < 1024) ? Wxi[k * 1024 + j] : Wxi[(k + LNF) * 1024 + (j - 1024)];
    g_W2b[idx] = __float2bfloat16(v);
}

// ---------------- CSR build ----------------
__global__ void count_kernel(const int* __restrict__ Xn, int E) {
    int e = blockIdx.x * blockDim.x + threadIdx.x;
    if (e < E) atomicAdd(&g_cnt[Xn[e]], 1);
}

__global__ __launch_bounds__(SCAN_BLK) void scan1_kernel(int V) {
    __shared__ int s[SCAN_BLK];
    int i = blockIdx.x * SCAN_BLK + threadIdx.x;
    s[threadIdx.x] = (i < V) ? g_cnt[i] : 0;
    __syncthreads();
#pragma unroll
    for (int off = SCAN_BLK / 2; off > 0; off >>= 1) {
        if (threadIdx.x < off) s[threadIdx.x] += s[threadIdx.x + off];
        __syncthreads();
    }
    if (threadIdx.x == 0) g_bsum[blockIdx.x] = s[0];
}

__global__ __launch_bounds__(128) void scan2_kernel(int nb, int V) {
    __shared__ int s[128];
    int t = threadIdx.x;
    int v = (t < nb) ? g_bsum[t] : 0;
    s[t] = v;
    __syncthreads();
#pragma unroll
    for (int off = 1; off < 128; off <<= 1) {
        int x = (t >= off) ? s[t - off] : 0;
        __syncthreads();
        s[t] += x;
        __syncthreads();
    }
    if (t < nb) g_bsum[t] = s[t] - v;        // exclusive
    if (t == 127) g_off[V] = s[127];          // total
}

__global__ __launch_bounds__(SCAN_BLK) void scan3_kernel(int V) {
    __shared__ int s[SCAN_BLK];
    int i = blockIdx.x * SCAN_BLK + threadIdx.x;
    int v = (i < V) ? g_cnt[i] : 0;
    s[threadIdx.x] = v;
    __syncthreads();
#pragma unroll
    for (int off = 1; off < SCAN_BLK; off <<= 1) {
        int x = (threadIdx.x >= off) ? s[threadIdx.x - off] : 0;
        __syncthreads();
        s[threadIdx.x] += x;
        __syncthreads();
    }
    if (i < V) {
        g_off[i]  = g_bsum[blockIdx.x] + s[threadIdx.x] - v;   // exclusive
        g_fill[i] = 0;
    }
}

__global__ void fill_kernel(const int* __restrict__ Xn, const int* __restrict__ Xe,
                            const float* __restrict__ dg, int E) {
    int e = blockIdx.x * blockDim.x + threadIdx.x;
    if (e >= E) return;
    int u = Xn[e];
    int pos = g_off[u] + atomicAdd(&g_fill[u], 1);
    g_ev[pos]  = Xe[e];
    g_esc[pos] = MU_OVER_S / dg[e];
}

// ---------------- bf16 MMA GEMM: PQ[M x 2048] = featbf[M x 128] @ W2b ----------------
// Block tile 128(M) x 256(N), full K=128 staged once. 8 warps = 2(M) x 4(N),
// each warp 64x64 => 4 ldsm(A) + 4 ldsm(B) per 32 mma per k-step.
#define AS_STRIDE 136                      // halves (272B rows, conflict-free)
#define BS_STRIDE 264                      // halves (528B rows, conflict-free)
#define SMEM_B_HALVES (128 * AS_STRIDE)    // A region size in halves
#define GEMM_SMEM_BYTES ((128 * AS_STRIDE + 128 * BS_STRIDE) * 2)   // 102400 B

__device__ __forceinline__ void ldsm_x4(uint32_t& r0, uint32_t& r1, uint32_t& r2, uint32_t& r3,
                                        uint32_t addr) {
    asm volatile("ldmatrix.sync.aligned.m8n8.x4.shared.b16 {%0,%1,%2,%3}, [%4];"
                 : "=r"(r0), "=r"(r1), "=r"(r2), "=r"(r3) : "r"(addr));
}
__device__ __forceinline__ void ldsm_x4_t(uint32_t& r0, uint32_t& r1, uint32_t& r2, uint32_t& r3,
                                          uint32_t addr) {
    asm volatile("ldmatrix.sync.aligned.m8n8.x4.trans.shared.b16 {%0,%1,%2,%3}, [%4];"
                 : "=r"(r0), "=r"(r1), "=r"(r2), "=r"(r3) : "r"(addr));
}
__device__ __forceinline__ void mma_bf16(float* c, const uint32_t* a, uint32_t b0, uint32_t b1) {
    asm volatile(
        "mma.sync.aligned.m16n8k16.row.col.f32.bf16.bf16.f32 "
        "{%0,%1,%2,%3}, {%4,%5,%6,%7}, {%8,%9}, {%0,%1,%2,%3};\n"
        : "+f"(c[0]), "+f"(c[1]), "+f"(c[2]), "+f"(c[3])
        : "r"(a[0]), "r"(a[1]), "r"(a[2]), "r"(a[3]), "r"(b0), "r"(b1));
}
__device__ __forceinline__ void cp_async16(uint32_t saddr, const void* gaddr) {
    asm volatile("cp.async.cg.shared.global [%0], [%1], 16;" :: "r"(saddr), "l"(gaddr));
}

__global__ __launch_bounds__(256, 1) void gemm_bf16_kernel(const float* __restrict__ bxi, int M) {
    extern __shared__ __nv_bfloat16 smem[];

    const int tid  = threadIdx.x;
    const int warp = tid >> 5;
    const int lane = tid & 31;
    const int g    = lane >> 2;
    const int t4   = lane & 3;
    const int wm   = warp & 1;       // 0..1 over M (64 rows each)
    const int wn   = warp >> 1;      // 0..3 over N (64 cols each)
    const int row0 = blockIdx.y * 128;
    const int col0 = blockIdx.x * 256;

    uint32_t smem_base;
    asm("{ .reg .u64 t; cvta.to.shared.u64 t, %1; cvt.u32.u64 %0, t; }"
        : "=r"(smem_base) : "l"(smem));
    const uint32_t b_base = smem_base + SMEM_B_HALVES * 2;

    // Stage A: 128 rows x 16 segs of 16B = 2048 chunks, 8/thread.
#pragma unroll
    for (int i = 0; i < 8; ++i) {
        int c = tid + i * 256;
        int r = c >> 4;
        int seg = c & 15;
        int grow = row0 + r; if (grow >= M) grow = M - 1;
        cp_async16(smem_base + (uint32_t)(r * AS_STRIDE + seg * 8) * 2,
                   g_fb + (size_t)grow * LNF + seg * 8);
    }
    // Stage B: 128 k-rows x 32 segs of 16B = 4096 chunks, 16/thread.
#pragma unroll
    for (int i = 0; i < 16; ++i) {
        int c = tid + i * 256;
        int k = c >> 5;
        int seg = c & 31;
        cp_async16(b_base + (uint32_t)(k * BS_STRIDE + seg * 8) * 2,
                   g_W2b + (size_t)k * NPQ + col0 + seg * 8);
    }
    asm volatile("cp.async.commit_group;");
    asm volatile("cp.async.wait_group 0;");
    __syncthreads();

    float acc[4][8][4];
#pragma unroll
    for (int mt = 0; mt < 4; ++mt)
#pragma unroll
        for (int nt = 0; nt < 8; ++nt)
#pragma unroll
            for (int r = 0; r < 4; ++r) acc[mt][nt][r] = 0.0f;

#pragma unroll
    for (int ks = 0; ks < 8; ++ks) {
        const int kb = ks * 16;
        uint32_t a[4][4];
#pragma unroll
        for (int mt = 0; mt < 4; ++mt) {
            int ar = wm * 64 + mt * 16;
            uint32_t addr = smem_base +
                (uint32_t)((ar + (lane & 15)) * AS_STRIDE + kb + ((lane >> 4) << 3)) * 2;
            ldsm_x4(a[mt][0], a[mt][1], a[mt][2], a[mt][3], addr);
        }
#pragma unroll
        for (int np = 0; np < 4; ++np) {          // each covers n16 = two n8 tiles
            int nc = wn * 64 + np * 16;
            uint32_t b0, b1, b2, b3;
            uint32_t addr = b_base +
                (uint32_t)((kb + (lane & 15)) * BS_STRIDE + nc + ((lane >> 4) << 3)) * 2;
            ldsm_x4_t(b0, b1, b2, b3, addr);
#pragma unroll
            for (int mt = 0; mt < 4; ++mt) {
                mma_bf16(acc[mt][np * 2],     a[mt], b0, b1);
                mma_bf16(acc[mt][np * 2 + 1], a[mt], b2, b3);
            }
        }
    }

    // epilogue: add bxi (cols < 1024), streaming-store fp16
#pragma unroll
    for (int mt = 0; mt < 4; ++mt) {
        int rlo = row0 + wm * 64 + mt * 16 + g;
#pragma unroll
        for (int nt = 0; nt < 8; ++nt) {
            int c = col0 + wn * 64 + nt * 8 + 2 * t4;
            float b0 = 0.f, b1 = 0.f;
            if (c < 1024) { b0 = __ldg(&bxi[c]); b1 = __ldg(&bxi[c + 1]); }
            if (rlo < M)
                __stcs((__half2*)(g_PQh + (size_t)rlo * NPQ + c),
                       __floats2half2_rn(acc[mt][nt][0] + b0, acc[mt][nt][1] + b1));
            if (rlo + 8 < M)
                __stcs((__half2*)(g_PQh + (size_t)(rlo + 8) * NPQ + c),
                       __floats2half2_rn(acc[mt][nt][2] + b0, acc[mt][nt][3] + b1));
        }
    }
}

// ---------------- R kernel (fp32) + fused feat->bf16 conversion ----------------
#define RNODES 48
__global__ __launch_bounds__(256) void r_kernel(const float* __restrict__ feat,
                                                const float* __restrict__ Wrou,
                                                const float* __restrict__ brou, int V) {
    __shared__ float Ws[LNF * SS];
    __shared__ float fr[RNODES * LNF];
    const int tid = threadIdx.x;
    const int n0 = blockIdx.x * RNODES;

    for (int i = tid; i < LNF * SS; i += 256) Ws[i] = Wrou[i];
    for (int i = tid; i < RNODES * LNF / 4; i += 256) {
        int node = n0 + (i * 4) / LNF;
        if (node >= V) node = V - 1;
        int k = (i * 4) & (LNF - 1);
        *(float4*)&fr[i * 4] = *(const float4*)(feat + (size_t)node * LNF + k);
    }
    __syncthreads();

    for (int i = tid; i < RNODES * LNF / 2; i += 256) {
        int node = n0 + (i * 2) / LNF;
        if (node < V) {
            int k = (i * 2) & (LNF - 1);
            ((__nv_bfloat162*)(g_fb + (size_t)node * LNF + k))[0] =
                __floats2bfloat162_rn(fr[i * 2], fr[i * 2 + 1]);
        }
    }

    const int warp = tid >> 5, lane = tid & 31;
    float acc[6];
#pragma unroll
    for (int i = 0; i < 6; ++i) acc[i] = 0.0f;
    const float* fbase = &fr[warp * 6 * LNF];
#pragma unroll 16
    for (int k = 0; k < LNF; ++k) {
        float wv = Ws[k * SS + lane];
#pragma unroll
        for (int i = 0; i < 6; ++i) acc[i] = fmaf(fbase[i * LNF + k], wv, acc[i]);
    }
    float bb = brou[lane];
#pragma unroll
    for (int i = 0; i < 6; ++i) {
        int node = n0 + warp * 6 + i;
        if (node < V) g_R[node * SS + lane] = tanhf(acc[i] + bb);
    }
}

// ---------------- edge kernel: one warp per node, half of the S-rows per pass ----------------
// (exact round-7 version — fastest measured variant)
__global__ __launch_bounds__(256) void edge_half_kernel(int V, int pass) {
    __shared__ float rs[8][SS];
    const int warp = threadIdx.x >> 5;
    const int lane = threadIdx.x & 31;
    const int u = blockIdx.x * 8 + warp;
    if (u >= V) return;
    const int n = g_cnt[u];
    if (n == 0) return;
    const int start = g_off[u];

    rs[warp][lane] = g_R[u * SS + lane];
    __syncwarp();

    const int row = lane >> 1;            // 0..15 local output row
    const int jh  = (lane & 1) * 16;      // j offset 0 or 16
    const size_t eoff = (size_t)pass * 512 + row * 32 + jh;

    float rloc[16];
#pragma unroll
    for (int i = 0; i < 16; ++i) rloc[i] = rs[warp][jh + i];

    const uint4 pA = __ldcs((const uint4*)(g_PQh + (size_t)u * NPQ + eoff));
    const uint4 pB = __ldcs((const uint4*)(g_PQh + (size_t)u * NPQ + eoff + 8));

    float racc = 0.0f;
    for (int e = start; e < start + n; ++e) {
        const int v = __ldcs(&g_ev[e]);
        const float sc = __ldcs(&g_esc[e]);
        const __half* qrow = g_PQh + (size_t)v * NPQ + 1024 + eoff;
        uint4 qA = *(const uint4*)qrow;
        uint4 qB = *(const uint4*)(qrow + 8);

        float partial = 0.0f;
        const __half2* ph = (const __half2*)&pA;
        const __half2* qh = (const __half2*)&qA;
#pragma unroll
        for (int k = 0; k < 4; ++k) {
            float2 t = __half22float2(h2tanh_fast(__hadd2(ph[k], qh[k])));
            partial = fmaf(t.x, rloc[2 * k],     partial);
            partial = fmaf(t.y, rloc[2 * k + 1], partial);
        }
        ph = (const __half2*)&pB; qh = (const __half2*)&qB;
#pragma unroll
        for (int k = 0; k < 4; ++k) {
            float2 t = __half22float2(h2tanh_fast(__hadd2(ph[k], qh[k])));
            partial = fmaf(t.x, rloc[8 + 2 * k],     partial);
            partial = fmaf(t.y, rloc[8 + 2 * k + 1], partial);
        }
        racc = fmaf(partial, sc, racc);
    }

    racc += __shfl_down_sync(0xffffffffu, racc, 1, 2);
    if ((lane & 1) == 0)
        g_hacc[u * SS + pass * 16 + row] = racc;
}

// ---------------- output ----------------
__global__ __launch_bounds__(256) void out_kernel(const float* __restrict__ Wout,
                                                  const float* __restrict__ bout,
                                                  float* __restrict__ out, int V) {
    int gtid = blockIdx.x * blockDim.x + threadIdx.x;
    int vtx = gtid >> 5;
    int lane = threadIdx.x & 31;
    if (vtx >= V) return;

    float c = (float)g_cnt[vtx];
    float Hf = (c > 0.0f) ? c * (g_hacc[vtx * SS + lane] + g_R[vtx * SS + lane]) : 0.0f;

    float mine = 0.0f;
    float logits[CC];
#pragma unroll
    for (int j = 0; j < CC; ++j) {
        float p = Hf * Wout[lane * CC + j];
#pragma unroll
        for (int off = 16; off > 0; off >>= 1)
            p += __shfl_xor_sync(0xffffffffu, p, off);
        logits[j] = p + bout[j];
        if (j == lane) mine = logits[j];
    }
    float m = logits[0];
#pragma unroll
    for (int j = 1; j < CC; ++j) m = fmaxf(m, logits[j]);
    float se = 0.0f;
#pragma unroll
    for (int j = 0; j < CC; ++j) se += expf(logits[j] - m);
    float lse = m + logf(se);

    if (lane < CC) out[(size_t)vtx * CC + lane] = mine - lse;
}

// ---------------- launch ----------------
extern "C" void kernel_launch(void* const* d_in, const int* in_sizes, int n_in,
                              void* d_out, int out_size) {
    const float* feat = (const float*)d_in[0];
    const int*   Xn   = (const int*)d_in[1];
    const int*   Xe   = (const int*)d_in[2];
    const float* dg   = (const float*)d_in[3];
    const float* Wxi  = (const float*)d_in[4];
    const float* bxi  = (const float*)d_in[5];
    const float* Wrou = (const float*)d_in[6];
    const float* brou = (const float*)d_in[7];
    const float* Wout = (const float*)d_in[8];
    const float* bout = (const float*)d_in[9];
    float* out = (float*)d_out;

    const int V = in_sizes[0] / LNF;
    const int E = in_sizes[1];
    const int nb = (V + SCAN_BLK - 1) / SCAN_BLK;

    cudaFuncSetAttribute(gemm_bf16_kernel,
                         cudaFuncAttributeMaxDynamicSharedMemorySize, GEMM_SMEM_BYTES);

    pack_w2_kernel<<<(LNF * NPQ + 255) / 256, 256>>>(Wxi, V);   // also zeroes g_cnt
    count_kernel<<<(E + 255) / 256, 256>>>(Xn, E);
    scan1_kernel<<<nb, SCAN_BLK>>>(V);
    scan2_kernel<<<1, 128>>>(nb, V);
    scan3_kernel<<<nb, SCAN_BLK>>>(V);
    fill_kernel<<<(E + 255) / 256, 256>>>(Xn, Xe, dg, E);

    r_kernel<<<(V + RNODES - 1) / RNODES, 256>>>(feat, Wrou, brou, V);   // also writes g_fb

    dim3 ggrid(NPQ / 256, (V + 127) / 128);
    gemm_bf16_kernel<<<ggrid, 256, GEMM_SMEM_BYTES>>>(bxi, V);

    edge_half_kernel<<<(V + 7) / 8, 256>>>(V, 0);
    edge_half_kernel<<<(V + 7) / 8, 256>>>(V, 1);
    out_kernel<<<(V * 32 + 255) / 256, 256>>>(Wout, bout, out, V);
}

// round 10
// speedup vs baseline: 1.0763x; 1.0264x over previous
#include <cuda_runtime.h>
#include <cuda_fp16.h>
#include <cuda_bf16.h>
#include <math.h>
#include <stdint.h>

#define LNF 128      // feat dim
#define SS  32       // stat dim
#define CC  10       // classes
#define NPQ 2048     // GEMM N: P(1024) || Q(1024)
#define MAXV 50000
#define MAXE 200000
#define MU_OVER_S (0.9f / 32.0f)
#define SCAN_BLK 512
#define MAXB ((MAXV + SCAN_BLK - 1) / SCAN_BLK)   // 98

// -------- static device scratch --------
__device__ __half         g_Ph[(size_t)MAXV * 1024];   // fp16 P (bxi folded), 102 MB
__device__ uint8_t        g_Qf8[(size_t)MAXV * 1024];  // e4m3 Q, 51 MB (L2-resident)
__device__ __nv_bfloat16  g_W2b[LNF * NPQ];            // bf16 [128 x 2048]
__device__ __nv_bfloat16  g_fb[(size_t)MAXV * LNF];    // bf16 feat
__device__ float          g_R[MAXV * SS];              // fp32 R
__device__ float          g_hacc[MAXV * SS];
__device__ int            g_cnt[MAXV];
__device__ int            g_fill[MAXV];
__device__ int            g_off[MAXV + 1];
__device__ int            g_bsum[MAXB];
__device__ int            g_ev[MAXE];
__device__ float          g_esc[MAXE];

__device__ __forceinline__ __half2 h2tanh_fast(__half2 x) {
    uint32_t xi = *(uint32_t*)&x, yi;
    asm("tanh.approx.f16x2 %0, %1;" : "=r"(yi) : "r"(xi));
    return *(__half2*)&yi;
}
__device__ __forceinline__ __half2 e4m3x2_to_h2(uint16_t x) {
    uint32_t r;
    asm("cvt.rn.f16x2.e4m3x2 %0, %1;" : "=r"(r) : "h"(x));
    return *(__half2*)&r;
}
// pack (v0 -> low byte, v1 -> high byte)
__device__ __forceinline__ uint16_t f32x2_to_e4m3x2(float v0, float v1) {
    uint16_t r;
    asm("cvt.rn.satfinite.e4m3x2.f32 %0, %1, %2;" : "=h"(r) : "f"(v1), "f"(v0));
    return r;
}

// ---------------- packing + cnt zero (fused) ----------------
__global__ void pack_w2_kernel(const float* __restrict__ Wxi, int V) {
    int idx = blockIdx.x * blockDim.x + threadIdx.x;
    if (idx < V) g_cnt[idx] = 0;
    if (idx >= LNF * NPQ) return;
    int k = idx / NPQ, j = idx - k * NPQ;
    float v = (j < 1024) ? Wxi[k * 1024 + j] : Wxi[(k + LNF) * 1024 + (j - 1024)];
    g_W2b[idx] = __float2bfloat16(v);
}

// ---------------- CSR build ----------------
__global__ void count_kernel(const int* __restrict__ Xn, int E) {
    int e = blockIdx.x * blockDim.x + threadIdx.x;
    if (e < E) atomicAdd(&g_cnt[Xn[e]], 1);
}

__global__ __launch_bounds__(SCAN_BLK) void scan1_kernel(int V) {
    __shared__ int s[SCAN_BLK];
    int i = blockIdx.x * SCAN_BLK + threadIdx.x;
    s[threadIdx.x] = (i < V) ? g_cnt[i] : 0;
    __syncthreads();
#pragma unroll
    for (int off = SCAN_BLK / 2; off > 0; off >>= 1) {
        if (threadIdx.x < off) s[threadIdx.x] += s[threadIdx.x + off];
        __syncthreads();
    }
    if (threadIdx.x == 0) g_bsum[blockIdx.x] = s[0];
}

__global__ __launch_bounds__(128) void scan2_kernel(int nb, int V) {
    __shared__ int s[128];
    int t = threadIdx.x;
    int v = (t < nb) ? g_bsum[t] : 0;
    s[t] = v;
    __syncthreads();
#pragma unroll
    for (int off = 1; off < 128; off <<= 1) {
        int x = (t >= off) ? s[t - off] : 0;
        __syncthreads();
        s[t] += x;
        __syncthreads();
    }
    if (t < nb) g_bsum[t] = s[t] - v;        // exclusive
    if (t == 127) g_off[V] = s[127];          // total
}

__global__ __launch_bounds__(SCAN_BLK) void scan3_kernel(int V) {
    __shared__ int s[SCAN_BLK];
    int i = blockIdx.x * SCAN_BLK + threadIdx.x;
    int v = (i < V) ? g_cnt[i] : 0;
    s[threadIdx.x] = v;
    __syncthreads();
#pragma unroll
    for (int off = 1; off < SCAN_BLK; off <<= 1) {
        int x = (threadIdx.x >= off) ? s[threadIdx.x - off] : 0;
        __syncthreads();
        s[threadIdx.x] += x;
        __syncthreads();
    }
    if (i < V) {
        g_off[i]  = g_bsum[blockIdx.x] + s[threadIdx.x] - v;   // exclusive
        g_fill[i] = 0;
    }
}

__global__ void fill_kernel(const int* __restrict__ Xn, const int* __restrict__ Xe,
                            const float* __restrict__ dg, int E) {
    int e = blockIdx.x * blockDim.x + threadIdx.x;
    if (e >= E) return;
    int u = Xn[e];
    int pos = g_off[u] + atomicAdd(&g_fill[u], 1);
    g_ev[pos]  = Xe[e];
    g_esc[pos] = MU_OVER_S / dg[e];
}

// ---------------- bf16 MMA GEMM (round-7 shape): 128x128 tile, 8 warps = 4(M) x 2(N) ----------------
#define AS_STRIDE 136
#define SMEM_B_OFF (128 * AS_STRIDE)
#define GEMM_SMEM_BYTES (2 * 128 * AS_STRIDE * 2)

__device__ __forceinline__ void ldsm_x4(uint32_t& r0, uint32_t& r1, uint32_t& r2, uint32_t& r3,
                                        uint32_t addr) {
    asm volatile("ldmatrix.sync.aligned.m8n8.x4.shared.b16 {%0,%1,%2,%3}, [%4];"
                 : "=r"(r0), "=r"(r1), "=r"(r2), "=r"(r3) : "r"(addr));
}
__device__ __forceinline__ void ldsm_x4_t(uint32_t& r0, uint32_t& r1, uint32_t& r2, uint32_t& r3,
                                          uint32_t addr) {
    asm volatile("ldmatrix.sync.aligned.m8n8.x4.trans.shared.b16 {%0,%1,%2,%3}, [%4];"
                 : "=r"(r0), "=r"(r1), "=r"(r2), "=r"(r3) : "r"(addr));
}
__device__ __forceinline__ void mma_bf16(float* c, const uint32_t* a, uint32_t b0, uint32_t b1) {
    asm volatile(
        "mma.sync.aligned.m16n8k16.row.col.f32.bf16.bf16.f32 "
        "{%0,%1,%2,%3}, {%4,%5,%6,%7}, {%8,%9}, {%0,%1,%2,%3};\n"
        : "+f"(c[0]), "+f"(c[1]), "+f"(c[2]), "+f"(c[3])
        : "r"(a[0]), "r"(a[1]), "r"(a[2]), "r"(a[3]), "r"(b0), "r"(b1));
}
__device__ __forceinline__ void cp_async16(uint32_t saddr, const void* gaddr) {
    asm volatile("cp.async.cg.shared.global [%0], [%1], 16;" :: "r"(saddr), "l"(gaddr));
}

__device__ __forceinline__ void epi_store_pair(int row, int c, float v0, float v1, int M,
                                               const float* __restrict__ bxi) {
    if (row >= M) return;
    if (c < 1024) {
        v0 += __ldg(&bxi[c]);
        v1 += __ldg(&bxi[c + 1]);
        __stcs((__half2*)(g_Ph + (size_t)row * 1024 + c), __floats2half2_rn(v0, v1));
    } else {
        int qc = c - 1024;
        *(uint16_t*)(g_Qf8 + (size_t)row * 1024 + qc) = f32x2_to_e4m3x2(v0, v1);
    }
}

__global__ __launch_bounds__(256) void gemm_bf16_kernel(const float* __restrict__ bxi, int M) {
    extern __shared__ __nv_bfloat16 smem[];

    const int tid  = threadIdx.x;
    const int warp = tid >> 5;
    const int lane = tid & 31;
    const int g    = lane >> 2;
    const int t4   = lane & 3;
    const int wm   = warp & 3;
    const int wn   = warp >> 2;
    const int row0 = blockIdx.y * 128;
    const int col0 = blockIdx.x * 128;

    uint32_t smem_base;
    asm("{ .reg .u64 t; cvta.to.shared.u64 t, %1; cvt.u32.u64 %0, t; }"
        : "=r"(smem_base) : "l"(smem));

#pragma unroll
    for (int i = 0; i < 8; ++i) {
        int c = tid + i * 256;
        int r = c >> 4;
        int seg = c & 15;
        int grow = row0 + r; if (grow >= M) grow = M - 1;
        cp_async16(smem_base + (uint32_t)(r * AS_STRIDE + seg * 8) * 2,
                   g_fb + (size_t)grow * LNF + seg * 8);
        cp_async16(smem_base + (uint32_t)(SMEM_B_OFF + r * AS_STRIDE + seg * 8) * 2,
                   g_W2b + (size_t)r * NPQ + col0 + seg * 8);
    }
    asm volatile("cp.async.commit_group;");
    asm volatile("cp.async.wait_group 0;");
    __syncthreads();

    float acc[2][8][4];
#pragma unroll
    for (int mt = 0; mt < 2; ++mt)
#pragma unroll
        for (int nt = 0; nt < 8; ++nt)
#pragma unroll
            for (int r = 0; r < 4; ++r) acc[mt][nt][r] = 0.0f;

#pragma unroll
    for (int ks = 0; ks < 8; ++ks) {
        const int kb = ks * 16;
        uint32_t a[2][4];
#pragma unroll
        for (int mt = 0; mt < 2; ++mt) {
            int ar = wm * 32 + mt * 16;
            uint32_t addr = smem_base +
                (uint32_t)((ar + (lane & 15)) * AS_STRIDE + kb + ((lane >> 4) << 3)) * 2;
            ldsm_x4(a[mt][0], a[mt][1], a[mt][2], a[mt][3], addr);
        }
#pragma unroll
        for (int np = 0; np < 4; ++np) {
            int nc = wn * 64 + np * 16;
            uint32_t b0, b1, b2, b3;
            uint32_t addr = smem_base +
                (uint32_t)(SMEM_B_OFF + (kb + (lane & 15)) * AS_STRIDE + nc + ((lane >> 4) << 3)) * 2;
            ldsm_x4_t(b0, b1, b2, b3, addr);
#pragma unroll
            for (int mt = 0; mt < 2; ++mt) {
                mma_bf16(acc[mt][np * 2],     a[mt], b0, b1);
                mma_bf16(acc[mt][np * 2 + 1], a[mt], b2, b3);
            }
        }
    }

#pragma unroll
    for (int mt = 0; mt < 2; ++mt) {
        int rlo = row0 + wm * 32 + mt * 16 + g;
#pragma unroll
        for (int nt = 0; nt < 8; ++nt) {
            int c = col0 + wn * 64 + nt * 8 + 2 * t4;
            epi_store_pair(rlo,     c, acc[mt][nt][0], acc[mt][nt][1], M, bxi);
            epi_store_pair(rlo + 8, c, acc[mt][nt][2], acc[mt][nt][3], M, bxi);
        }
    }
}

// ---------------- R kernel (fp32) + fused feat->bf16 conversion ----------------
#define RNODES 48
__global__ __launch_bounds__(256) void r_kernel(const float* __restrict__ feat,
                                                const float* __restrict__ Wrou,
                                                const float* __restrict__ brou, int V) {
    __shared__ float Ws[LNF * SS];
    __shared__ float fr[RNODES * LNF];
    const int tid = threadIdx.x;
    const int n0 = blockIdx.x * RNODES;

    for (int i = tid; i < LNF * SS; i += 256) Ws[i] = Wrou[i];
    for (int i = tid; i < RNODES * LNF / 4; i += 256) {
        int node = n0 + (i * 4) / LNF;
        if (node >= V) node = V - 1;
        int k = (i * 4) & (LNF - 1);
        *(float4*)&fr[i * 4] = *(const float4*)(feat + (size_t)node * LNF + k);
    }
    __syncthreads();

    for (int i = tid; i < RNODES * LNF / 2; i += 256) {
        int node = n0 + (i * 2) / LNF;
        if (node < V) {
            int k = (i * 2) & (LNF - 1);
            ((__nv_bfloat162*)(g_fb + (size_t)node * LNF + k))[0] =
                __floats2bfloat162_rn(fr[i * 2], fr[i * 2 + 1]);
        }
    }

    const int warp = tid >> 5, lane = tid & 31;
    float acc[6];
#pragma unroll
    for (int i = 0; i < 6; ++i) acc[i] = 0.0f;
    const float* fbase = &fr[warp * 6 * LNF];
#pragma unroll 16
    for (int k = 0; k < LNF; ++k) {
        float wv = Ws[k * SS + lane];
#pragma unroll
        for (int i = 0; i < 6; ++i) acc[i] = fmaf(fbase[i * LNF + k], wv, acc[i]);
    }
    float bb = brou[lane];
#pragma unroll
    for (int i = 0; i < 6; ++i) {
        int node = n0 + warp * 6 + i;
        if (node < V) g_R[node * SS + lane] = tanhf(acc[i] + bb);
    }
}

// ---------------- edge kernel: single pass, lane = output row, Q in fp8 ----------------
// lane i: hacc[u][i] = sum_e sc_e * sum_j tanh(P[u][i*32+j] + Q[v][i*32+j]) * R[u][j]
__global__ __launch_bounds__(256) void edge_kernel(int V) {
    __shared__ float rs[8][SS];
    const int warp = threadIdx.x >> 5;
    const int lane = threadIdx.x & 31;
    const int u = blockIdx.x * 8 + warp;
    if (u >= V) return;
    const int n = g_cnt[u];
    if (n == 0) return;
    const int start = g_off[u];

    rs[warp][lane] = g_R[u * SS + lane];
    __syncwarp();

    // resident P slice: 32 fp16 = 64B (streamed, evict-first)
    const uint4* Pp = (const uint4*)(g_Ph + (size_t)u * 1024 + lane * 32);
    uint4 pr[4] = {__ldcs(Pp), __ldcs(Pp + 1), __ldcs(Pp + 2), __ldcs(Pp + 3)};
    const __half2* ph = (const __half2*)pr;      // 16 half2

    float racc = 0.0f;
    for (int e = start; e < start + n; ++e) {
        const int v = g_ev[e];
        const float sc = g_esc[e];
        const uint4* qp = (const uint4*)(g_Qf8 + (size_t)v * 1024 + lane * 32);
        uint4 q0 = qp[0];                          // 16 fp8
        uint4 q1 = qp[1];                          // 16 fp8
        const uint16_t* qa = (const uint16_t*)&q0; // 8 e4m3 pairs
        const uint16_t* qb = (const uint16_t*)&q1;

        float partial = 0.0f;
#pragma unroll
        for (int k = 0; k < 8; ++k) {
            float2 t = __half22float2(h2tanh_fast(__hadd2(ph[k], e4m3x2_to_h2(qa[k]))));
            partial = fmaf(t.x, rs[warp][2 * k],     partial);
            partial = fmaf(t.y, rs[warp][2 * k + 1], partial);
        }
#pragma unroll
        for (int k = 0; k < 8; ++k) {
            float2 t = __half22float2(h2tanh_fast(__hadd2(ph[8 + k], e4m3x2_to_h2(qb[k]))));
            partial = fmaf(t.x, rs[warp][16 + 2 * k], partial);
            partial = fmaf(t.y, rs[warp][17 + 2 * k], partial);
        }
        racc = fmaf(partial, sc, racc);
    }
    g_hacc[u * SS + lane] = racc;
}

// ---------------- output ----------------
__global__ __launch_bounds__(256) void out_kernel(const float* __restrict__ Wout,
                                                  const float* __restrict__ bout,
                                                  float* __restrict__ out, int V) {
    int gtid = blockIdx.x * blockDim.x + threadIdx.x;
    int vtx = gtid >> 5;
    int lane = threadIdx.x & 31;
    if (vtx >= V) return;

    float c = (float)g_cnt[vtx];
    float Hf = (c > 0.0f) ? c * (g_hacc[vtx * SS + lane] + g_R[vtx * SS + lane]) : 0.0f;

    float mine = 0.0f;
    float logits[CC];
#pragma unroll
    for (int j = 0; j < CC; ++j) {
        float p = Hf * Wout[lane * CC + j];
#pragma unroll
        for (int off = 16; off > 0; off >>= 1)
            p += __shfl_xor_sync(0xffffffffu, p, off);
        logits[j] = p + bout[j];
        if (j == lane) mine = logits[j];
    }
    float m = logits[0];
#pragma unroll
    for (int j = 1; j < CC; ++j) m = fmaxf(m, logits[j]);
    float se = 0.0f;
#pragma unroll
    for (int j = 0; j < CC; ++j) se += expf(logits[j] - m);
    float lse = m + logf(se);

    if (lane < CC) out[(size_t)vtx * CC + lane] = mine - lse;
}

// ---------------- launch ----------------
extern "C" void kernel_launch(void* const* d_in, const int* in_sizes, int n_in,
                              void* d_out, int out_size) {
    const float* feat = (const float*)d_in[0];
    const int*   Xn   = (const int*)d_in[1];
    const int*   Xe   = (const int*)d_in[2];
    const float* dg   = (const float*)d_in[3];
    const float* Wxi  = (const float*)d_in[4];
    const float* bxi  = (const float*)d_in[5];
    const float* Wrou = (const float*)d_in[6];
    const float* brou = (const float*)d_in[7];
    const float* Wout = (const float*)d_in[8];
    const float* bout = (const float*)d_in[9];
    float* out = (float*)d_out;

    const int V = in_sizes[0] / LNF;
    const int E = in_sizes[1];
    const int nb = (V + SCAN_BLK - 1) / SCAN_BLK;

    cudaFuncSetAttribute(gemm_bf16_kernel,
                         cudaFuncAttributeMaxDynamicSharedMemorySize, GEMM_SMEM_BYTES);

    pack_w2_kernel<<<(LNF * NPQ + 255) / 256, 256>>>(Wxi, V);   // also zeroes g_cnt
    count_kernel<<<(E + 255) / 256, 256>>>(Xn, E);
    scan1_kernel<<<nb, SCAN_BLK>>>(V);
    scan2_kernel<<<1, 128>>>(nb, V);
    scan3_kernel<<<nb, SCAN_BLK>>>(V);
    fill_kernel<<<(E + 255) / 256, 256>>>(Xn, Xe, dg, E);

    r_kernel<<<(V + RNODES - 1) / RNODES, 256>>>(feat, Wrou, brou, V);   // also writes g_fb

    dim3 ggrid(NPQ / 128, (V + 127) / 128);
    gemm_bf16_kernel<<<ggrid, 256, GEMM_SMEM_BYTES>>>(bxi, V);

    edge_kernel<<<(V + 7) / 8, 256>>>(V);
    out_kernel<<<(V * 32 + 255) / 256, 256>>>(Wout, bout, out, V);
}